// round 16
// baseline (speedup 1.0000x reference)
#include <cuda_runtime.h>
#include <cuda_fp16.h>
#include <cstdint>

// ---------------------------------------------------------------------------
// Problem constants
// ---------------------------------------------------------------------------
#define SVOX 262144        // 64^3 voxels per batch
#define NB   2
#define GCH  128
#define XCH  64
#define NCTA1 4096         // NB * 2048 tiles of 128 voxels
#define EPSV 1e-5f

// SMEM strides (halfs) — R9 values
#define SA_STRIDE 136      // A tiles [k][v], 128 v + 8 pad
#define SWG_STRIDE 136     // Wg rows [n][k], 128 k + 8 pad
#define SWX_STRIDE 72      // Wx rows [n][k], 64 k + 8 pad

// pass1g smem layout (bytes)
#define G_OFF_A 0                                  // 128*136*2 = 34816
#define G_OFF_W (G_OFF_A + 128 * SA_STRIDE * 2)    // 64*136*2  = 17408
#define G_OFF_RED (G_OFF_W + 64 * SWG_STRIDE * 2)  // 8*16*4    = 512
#define G_SMEM (G_OFF_RED + 8 * 16 * 4)            // 52736 -> 4 CTAs/SM (smem-wise)

// pass1x smem layout (bytes)
#define X_OFF_A 0                                  // 64*136*2 = 17408
#define X_OFF_W (X_OFF_A + 64 * SA_STRIDE * 2)     // 64*72*2  = 9216
#define X_OFF_RED (X_OFF_W + 64 * SWX_STRIDE * 2)
#define X_SMEM (X_OFF_RED + 8 * 16 * 4)            // 27136 -> 5 CTAs/SM (smem-wise)

// ---------------------------------------------------------------------------
// Device scratch (allocation-free __device__ globals)
// ---------------------------------------------------------------------------
__device__ uint32_t g_sg[(size_t)NCTA1 * 4096];   // yg fp16x2, flat per-thread layout
__device__ uint32_t g_sx[(size_t)NCTA1 * 4096];   // yx fp16x2
__device__ float    g_p[NB * SVOX];               // psi-conv output p
__device__ float    g_acc[NB * 32];               // [b][ sG(8) qG(8) sX(8) qX(8) ]
__device__ float    g_accP[NB * 2];               // p sum/sumsq per batch
__device__ __align__(16) __half g_wg16[64 * SWG_STRIDE];   // prepacked fp16 Wg
__device__ __align__(16) __half g_wx16[64 * SWX_STRIDE];   // prepacked fp16 Wx

// ---------------------------------------------------------------------------
// PTX helpers
// ---------------------------------------------------------------------------
__device__ __forceinline__ uint32_t smem_to_u32(const void* smem_ptr) {
    uint32_t addr;
    asm("{ .reg .u64 tmp; cvta.to.shared.u64 tmp, %1; cvt.u32.u64 %0, tmp; }"
        : "=r"(addr) : "l"(smem_ptr));
    return addr;
}

__device__ __forceinline__ void mma16816(float* d,
                                         uint32_t a0, uint32_t a1, uint32_t a2, uint32_t a3,
                                         uint32_t b0, uint32_t b1) {
    asm volatile(
        "mma.sync.aligned.m16n8k16.row.col.f32.f16.f16.f32 "
        "{%0,%1,%2,%3}, {%4,%5,%6,%7}, {%8,%9}, {%0,%1,%2,%3};"
        : "+f"(d[0]), "+f"(d[1]), "+f"(d[2]), "+f"(d[3])
        : "r"(a0), "r"(a1), "r"(a2), "r"(a3), "r"(b0), "r"(b1));
}

__device__ __forceinline__ void ldsm_x4_trans(uint32_t& r0, uint32_t& r1,
                                              uint32_t& r2, uint32_t& r3,
                                              uint32_t addr) {
    asm volatile(
        "ldmatrix.sync.aligned.m8n8.x4.trans.shared.b16 {%0,%1,%2,%3}, [%4];"
        : "=r"(r0), "=r"(r1), "=r"(r2), "=r"(r3) : "r"(addr));
}

__device__ __forceinline__ uint32_t packf2(float a, float b) {
    __half2 h = __floats2half2_rn(a, b);
    return *reinterpret_cast<uint32_t*>(&h);
}

// ---------------------------------------------------------------------------
// setup: zero stat accumulators + prepack weights to fp16 padded images
// ---------------------------------------------------------------------------
__global__ void setup_kernel(const float* __restrict__ Wg_w,
                             const float* __restrict__ Wx_w) {
    const int tid = threadIdx.x;
    if (tid < NB * 32) g_acc[tid] = 0.0f;
    if (tid < NB * 2)  g_accP[tid] = 0.0f;
    for (int i = tid; i < 64 * SWG_STRIDE; i += 256) {
        int o = i / SWG_STRIDE, k = i % SWG_STRIDE;
        g_wg16[i] = (k < 128) ? __float2half_rn(Wg_w[o * 128 + k]) : __float2half_rn(0.0f);
    }
    for (int i = tid; i < 64 * SWX_STRIDE; i += 256) {
        int o = i / SWX_STRIDE, k = i % SWX_STRIDE;
        g_wx16[i] = (k < 64) ? __float2half_rn(Wx_w[o * 64 + k]) : __float2half_rn(0.0f);
    }
}

// ---------------------------------------------------------------------------
// pass1g: g conv (K=128) via mma.sync + GN stats + fp16 scratch (__stcs).
// occ bumped to 4 CTAs/SM (64-reg cap).
// ---------------------------------------------------------------------------
__global__ void __launch_bounds__(256, 4)
pass1g_kernel(const float* __restrict__ gin) {
    extern __shared__ char smem[];
    __half* sA = (__half*)(smem + G_OFF_A);
    __half* sW = (__half*)(smem + G_OFF_W);
    float*  red = (float*)(smem + G_OFF_RED);

    const int tid = threadIdx.x;
    const int w = tid >> 5, lane = tid & 31;
    const int gr = lane >> 2, tg = lane & 3;
    const int cta = blockIdx.x;
    const int b = cta >> 11;
    const int tile = cta & 2047;
    const int vb = w * 16;

    {
        const int r = tid >> 5;
        const int l = tid & 31;
        const float4* g4 = (const float4*)gin + ((size_t)b * GCH) * (SVOX / 4)
                         + (size_t)tile * 32 + l;
        #pragma unroll
        for (int it = 0; it < 16; ++it) {
            int c = it * 8 + r;
            float4 v = __ldcs(&g4[(size_t)c * (SVOX / 4)]);
            uint2 pk;
            pk.x = packf2(v.x, v.y);
            pk.y = packf2(v.z, v.w);
            *(uint2*)&sA[c * SA_STRIDE + l * 4] = pk;
        }
    }
    {
        const uint4* wg = (const uint4*)g_wg16;
        uint4* dg = (uint4*)sW;
        for (int i = tid; i < 1088; i += 256) dg[i] = wg[i];
    }
    __syncthreads();

    const uint32_t aoff2 = (uint32_t)((((lane & 7) + ((lane >> 4) & 1) * 8) * SA_STRIDE
                          + vb + ((lane >> 3) & 1) * 8) * 2);
    const uint32_t sA_u = smem_to_u32(sA) + aoff2;
    const size_t sbase4 = ((size_t)cta << 10) + (size_t)tid * 4;   // uint4 index

    #pragma unroll
    for (int half = 0; half < 2; ++half) {
        float acc[4][4];
        #pragma unroll
        for (int nt = 0; nt < 4; ++nt)
            #pragma unroll
            for (int j = 0; j < 4; ++j) acc[nt][j] = 0.0f;

        #pragma unroll
        for (int ks = 0; ks < 8; ++ks) {
            uint32_t a0, a1, a2, a3;
            ldsm_x4_trans(a0, a1, a2, a3, sA_u + (uint32_t)(ks * 16 * SA_STRIDE * 2));
            #pragma unroll
            for (int nt = 0; nt < 4; ++nt) {
                int n = (half * 4 + nt) * 8 + gr;
                uint32_t b0 = *(const uint32_t*)&sW[n * SWG_STRIDE + ks * 16 + 2 * tg];
                uint32_t b1 = *(const uint32_t*)&sW[n * SWG_STRIDE + ks * 16 + 8 + 2 * tg];
                mma16816(acc[nt], a0, a1, a2, a3, b0, b1);
            }
        }
        float stats[8];
        uint4 st[2];
        #pragma unroll
        for (int nt = 0; nt < 4; ++nt) {
            float d0 = acc[nt][0], d1 = acc[nt][1], d2 = acc[nt][2], d3 = acc[nt][3];
            stats[nt]     = d0 + d1 + d2 + d3;
            stats[4 + nt] = d0 * d0 + d1 * d1 + d2 * d2 + d3 * d3;
            ((uint32_t*)st)[nt * 2 + 0] = packf2(d0, d1);   // voxel vb+gr
            ((uint32_t*)st)[nt * 2 + 1] = packf2(d2, d3);   // voxel vb+gr+8
        }
        uint4* outg = (uint4*)g_sg + sbase4 + half * 2;
        __stcs(&outg[0], st[0]);
        __stcs(&outg[1], st[1]);

        #pragma unroll
        for (int j = 0; j < 4; ++j) {
            float t0 = stats[j], t1 = stats[4 + j];
            #pragma unroll
            for (int off = 16; off > 0; off >>= 1) {
                t0 += __shfl_xor_sync(0xFFFFFFFFu, t0, off);
                t1 += __shfl_xor_sync(0xFFFFFFFFu, t1, off);
            }
            if (lane == 0) {
                red[w * 16 + half * 4 + j]     = t0;
                red[w * 16 + 8 + half * 4 + j] = t1;
            }
        }
    }
    __syncthreads();
    if (tid < 16) {
        float t = 0.0f;
        #pragma unroll
        for (int ww = 0; ww < 8; ++ww) t += red[ww * 16 + tid];
        atomicAdd(&g_acc[b * 32 + tid], t);       // sG[8], qG[8]
    }
}

// ---------------------------------------------------------------------------
// pass1x: x conv (K=64), occ bumped to 5 CTAs/SM (51-reg cap).
// ---------------------------------------------------------------------------
__global__ void __launch_bounds__(256, 5)
pass1x_kernel(const float* __restrict__ xin) {
    extern __shared__ char smem[];
    __half* sA = (__half*)(smem + X_OFF_A);
    __half* sW = (__half*)(smem + X_OFF_W);
    float*  red = (float*)(smem + X_OFF_RED);

    const int tid = threadIdx.x;
    const int w = tid >> 5, lane = tid & 31;
    const int gr = lane >> 2, tg = lane & 3;
    const int cta = blockIdx.x;
    const int b = cta >> 11;
    const int tile = cta & 2047;
    const int vb = w * 16;

    {
        const int r = tid >> 5;
        const int l = tid & 31;
        const float4* x4 = (const float4*)xin + ((size_t)b * XCH) * (SVOX / 4)
                         + (size_t)tile * 32 + l;
        #pragma unroll
        for (int it = 0; it < 8; ++it) {
            int c = it * 8 + r;
            float4 v = __ldcs(&x4[(size_t)c * (SVOX / 4)]);
            uint2 pk;
            pk.x = packf2(v.x, v.y);
            pk.y = packf2(v.z, v.w);
            *(uint2*)&sA[c * SA_STRIDE + l * 4] = pk;
        }
    }
    {
        const uint4* wx = (const uint4*)g_wx16;
        uint4* dx = (uint4*)sW;
        for (int i = tid; i < 576; i += 256) dx[i] = wx[i];
    }
    __syncthreads();

    const uint32_t aoff2 = (uint32_t)((((lane & 7) + ((lane >> 4) & 1) * 8) * SA_STRIDE
                          + vb + ((lane >> 3) & 1) * 8) * 2);
    const uint32_t sA_u = smem_to_u32(sA) + aoff2;
    const size_t sbase4 = ((size_t)cta << 10) + (size_t)tid * 4;

    #pragma unroll
    for (int half = 0; half < 2; ++half) {
        float acc[4][4];
        #pragma unroll
        for (int nt = 0; nt < 4; ++nt)
            #pragma unroll
            for (int j = 0; j < 4; ++j) acc[nt][j] = 0.0f;

        #pragma unroll
        for (int ks = 0; ks < 4; ++ks) {
            uint32_t a0, a1, a2, a3;
            ldsm_x4_trans(a0, a1, a2, a3, sA_u + (uint32_t)(ks * 16 * SA_STRIDE * 2));
            #pragma unroll
            for (int nt = 0; nt < 4; ++nt) {
                int n = (half * 4 + nt) * 8 + gr;
                uint32_t b0 = *(const uint32_t*)&sW[n * SWX_STRIDE + ks * 16 + 2 * tg];
                uint32_t b1 = *(const uint32_t*)&sW[n * SWX_STRIDE + ks * 16 + 8 + 2 * tg];
                mma16816(acc[nt], a0, a1, a2, a3, b0, b1);
            }
        }
        float stats[8];
        uint4 st[2];
        #pragma unroll
        for (int nt = 0; nt < 4; ++nt) {
            float d0 = acc[nt][0], d1 = acc[nt][1], d2 = acc[nt][2], d3 = acc[nt][3];
            stats[nt]     = d0 + d1 + d2 + d3;
            stats[4 + nt] = d0 * d0 + d1 * d1 + d2 * d2 + d3 * d3;
            ((uint32_t*)st)[nt * 2 + 0] = packf2(d0, d1);
            ((uint32_t*)st)[nt * 2 + 1] = packf2(d2, d3);
        }
        uint4* outx = (uint4*)g_sx + sbase4 + half * 2;
        __stcs(&outx[0], st[0]);
        __stcs(&outx[1], st[1]);

        #pragma unroll
        for (int j = 0; j < 4; ++j) {
            float t0 = stats[j], t1 = stats[4 + j];
            #pragma unroll
            for (int off = 16; off > 0; off >>= 1) {
                t0 += __shfl_xor_sync(0xFFFFFFFFu, t0, off);
                t1 += __shfl_xor_sync(0xFFFFFFFFu, t1, off);
            }
            if (lane == 0) {
                red[w * 16 + half * 4 + j]     = t0;
                red[w * 16 + 8 + half * 4 + j] = t1;
            }
        }
    }
    __syncthreads();
    if (tid < 16) {
        float t = 0.0f;
        #pragma unroll
        for (int ww = 0; ww < 8; ++ww) t += red[ww * 16 + tid];
        atomicAdd(&g_acc[b * 32 + 16 + tid], t);   // sX[8], qX[8]
    }
}

// ---------------------------------------------------------------------------
// pass2: (finA folded in) GN + leaky + psi-dot -> p, and p stats.
// 8 tiles per CTA (grid 512): prologue/epilogue amortized 8x.
// ---------------------------------------------------------------------------
__global__ void __launch_bounds__(256)
pass2_kernel(const float* __restrict__ psi_w,
             const float* __restrict__ gw_g, const float* __restrict__ gb_g,
             const float* __restrict__ gw_x, const float* __restrict__ gb_x) {
    __shared__ float2 spG[64], spX[64];
    __shared__ float  spw[64];
    __shared__ float  red2[8][2];

    const int tid = threadIdx.x;
    const int w = tid >> 5, lane = tid & 31;
    const int gr = lane >> 2, tg = lane & 3;
    const int blk = blockIdx.x;            // 0..511
    const int b = blk >> 8;
    const int tile0 = (blk & 255) << 3;    // 8 consecutive tiles

    if (tid < 16) {
        int conv = tid >> 3, grp = tid & 7;
        float s = g_acc[b * 32 + conv * 16 + grp];
        float q = g_acc[b * 32 + conv * 16 + 8 + grp];
        const float inv = 1.0f / (8.0f * (float)SVOX);
        float mean = s * inv;
        float var = q * inv - mean * mean;
        float rs = rsqrtf(var + EPSV);
        const float* gw = conv ? gw_x : gw_g;
        const float* gb = conv ? gb_x : gb_g;
        float2* par = conv ? spX : spG;
        #pragma unroll
        for (int c = 0; c < 8; ++c) {
            int o = grp * 8 + c;
            float sc = rs * gw[o];
            par[o] = make_float2(sc, gb[o] - mean * sc);
        }
    }
    if (tid >= 64 && tid < 128) spw[tid - 64] = psi_w[tid - 64];
    __syncthreads();

    float accS = 0.0f, accQ = 0.0f;

    for (int t = 0; t < 8; ++t) {
        const int tile = tile0 + t;
        const int cta = b * 2048 + tile;
        const size_t sbase4 = ((size_t)cta << 10) + (size_t)tid * 4;
        const uint4* pg4 = (const uint4*)g_sg + sbase4;
        const uint4* px4 = (const uint4*)g_sx + sbase4;
        uint32_t rg[16], rx[16];
        #pragma unroll
        for (int k2 = 0; k2 < 4; ++k2) {
            uint4 vg = __ldcs(&pg4[k2]);
            rg[4 * k2 + 0] = vg.x; rg[4 * k2 + 1] = vg.y;
            rg[4 * k2 + 2] = vg.z; rg[4 * k2 + 3] = vg.w;
            uint4 vx = __ldcs(&px4[k2]);
            rx[4 * k2 + 0] = vx.x; rx[4 * k2 + 1] = vx.y;
            rx[4 * k2 + 2] = vx.z; rx[4 * k2 + 3] = vx.w;
        }

        float pp0 = 0.0f, pp1 = 0.0f;
        #pragma unroll
        for (int nt = 0; nt < 8; ++nt) {
            int c0 = nt * 8 + 2 * tg;
            float2 G0 = spG[c0], G1 = spG[c0 + 1];
            float2 X0 = spX[c0], X1 = spX[c0 + 1];
            float w0 = spw[c0], w1 = spw[c0 + 1];
            {
                float2 yg = __half22float2(*reinterpret_cast<__half2*>(&rg[nt * 2 + 0]));
                float2 yx = __half22float2(*reinterpret_cast<__half2*>(&rx[nt * 2 + 0]));
                float a0 = fmaf(yg.x, G0.x, G0.y) + fmaf(yx.x, X0.x, X0.y);
                float a1 = fmaf(yg.y, G1.x, G1.y) + fmaf(yx.y, X1.x, X1.y);
                a0 = fmaxf(a0, 0.01f * a0);
                a1 = fmaxf(a1, 0.01f * a1);
                pp0 = fmaf(w0, a0, pp0);
                pp0 = fmaf(w1, a1, pp0);
            }
            {
                float2 yg = __half22float2(*reinterpret_cast<__half2*>(&rg[nt * 2 + 1]));
                float2 yx = __half22float2(*reinterpret_cast<__half2*>(&rx[nt * 2 + 1]));
                float a0 = fmaf(yg.x, G0.x, G0.y) + fmaf(yx.x, X0.x, X0.y);
                float a1 = fmaf(yg.y, G1.x, G1.y) + fmaf(yx.y, X1.x, X1.y);
                a0 = fmaxf(a0, 0.01f * a0);
                a1 = fmaxf(a1, 0.01f * a1);
                pp1 = fmaf(w0, a0, pp1);
                pp1 = fmaf(w1, a1, pp1);
            }
        }
        pp0 += __shfl_xor_sync(0xFFFFFFFFu, pp0, 1);
        pp0 += __shfl_xor_sync(0xFFFFFFFFu, pp0, 2);
        pp1 += __shfl_xor_sync(0xFFFFFFFFu, pp1, 1);
        pp1 += __shfl_xor_sync(0xFFFFFFFFu, pp1, 2);

        const size_t voff = (size_t)b * SVOX + (size_t)tile * 128 + w * 16;
        if (tg == 0) g_p[voff + gr]     = pp0;
        if (tg == 1) g_p[voff + gr + 8] = pp1;

        float s = (tg == 0) ? pp0 : ((tg == 1) ? pp1 : 0.0f);
        accS += s;
        accQ += s * s;
    }

    #pragma unroll
    for (int off = 16; off > 0; off >>= 1) {
        accS += __shfl_xor_sync(0xFFFFFFFFu, accS, off);
        accQ += __shfl_xor_sync(0xFFFFFFFFu, accQ, off);
    }
    if (lane == 0) { red2[w][0] = accS; red2[w][1] = accQ; }
    __syncthreads();
    if (tid == 0) {
        float ts = 0.0f, tq = 0.0f;
        #pragma unroll
        for (int ww = 0; ww < 8; ++ww) { ts += red2[ww][0]; tq += red2[ww][1]; }
        atomicAdd(&g_accP[b * 2 + 0], ts);
        atomicAdd(&g_accP[b * 2 + 1], tq);
    }
}

// ---------------------------------------------------------------------------
// pass3 (R9): (finB folded) out = x * sigmoid(z). Grid 8192, 4 ch/thread.
// ---------------------------------------------------------------------------
__global__ void __launch_bounds__(256, 8)
pass3_kernel(const float* __restrict__ xin, float* __restrict__ out,
             const float* __restrict__ pgw, const float* __restrict__ pgb) {
    const int blk = blockIdx.x;                 // 8192
    const int b = blk >> 12;
    const int cchunk = (blk >> 8) & 15;
    const int q = ((blk & 255) << 8) + threadIdx.x;   // quad 0..65535

    float sB = g_accP[b * 2], qB = g_accP[b * 2 + 1];
    const float inv = 1.0f / (float)SVOX;
    float mean = sB * inv;
    float var = qB * inv - mean * mean;
    float rs = rsqrtf(var + EPSV);
    float zsc = rs * pgw[0];
    float zsh = pgb[0] - mean * zsc;

    const float4* xp = (const float4*)xin
                     + ((size_t)b * 64 + (size_t)cchunk * 4) * 65536 + q;
    float4* op = (float4*)out
               + ((size_t)b * 64 + (size_t)cchunk * 4) * 65536 + q;

    float4 pv = *((const float4*)g_p + (size_t)b * 65536 + q);
    float4 xv[4];
    #pragma unroll
    for (int c = 0; c < 4; c++) xv[c] = __ldcs(&xp[(size_t)c * 65536]);

    float4 ps;
    {
        float z0 = fmaf(pv.x, zsc, zsh);
        float z1 = fmaf(pv.y, zsc, zsh);
        float z2 = fmaf(pv.z, zsc, zsh);
        float z3 = fmaf(pv.w, zsc, zsh);
        ps.x = __fdividef(1.0f, 1.0f + __expf(-z0));
        ps.y = __fdividef(1.0f, 1.0f + __expf(-z1));
        ps.z = __fdividef(1.0f, 1.0f + __expf(-z2));
        ps.w = __fdividef(1.0f, 1.0f + __expf(-z3));
    }

    #pragma unroll
    for (int c = 0; c < 4; c++) {
        float4 ov;
        ov.x = xv[c].x * ps.x; ov.y = xv[c].y * ps.y;
        ov.z = xv[c].z * ps.z; ov.w = xv[c].w * ps.w;
        __stcs(&op[(size_t)c * 65536], ov);
    }
}

// ---------------------------------------------------------------------------
// launch
// ---------------------------------------------------------------------------
extern "C" void kernel_launch(void* const* d_in, const int* in_sizes, int n_in,
                              void* d_out, int out_size) {
    (void)in_sizes; (void)n_in; (void)out_size;
    const float* g        = (const float*)d_in[0];
    const float* x        = (const float*)d_in[1];
    const float* Wg_w     = (const float*)d_in[2];
    const float* Wg_gn_w  = (const float*)d_in[3];
    const float* Wg_gn_b  = (const float*)d_in[4];
    const float* Wx_w     = (const float*)d_in[5];
    const float* Wx_gn_w  = (const float*)d_in[6];
    const float* Wx_gn_b  = (const float*)d_in[7];
    const float* psi_w    = (const float*)d_in[8];
    const float* psi_gn_w = (const float*)d_in[9];
    const float* psi_gn_b = (const float*)d_in[10];
    float* out = (float*)d_out;

    cudaFuncSetAttribute(pass1g_kernel, cudaFuncAttributeMaxDynamicSharedMemorySize,
                         G_SMEM);
    cudaFuncSetAttribute(pass1x_kernel, cudaFuncAttributeMaxDynamicSharedMemorySize,
                         X_SMEM);

    setup_kernel<<<1, 256>>>(Wg_w, Wx_w);
    pass1g_kernel<<<NCTA1, 256, G_SMEM>>>(g);
    pass1x_kernel<<<NCTA1, 256, X_SMEM>>>(x);
    pass2_kernel<<<512, 256>>>(psi_w, Wg_gn_w, Wg_gn_b, Wx_gn_w, Wx_gn_b);
    pass3_kernel<<<8192, 256>>>(x, out, psi_gn_w, psi_gn_b);
}

// round 17
// speedup vs baseline: 1.0868x; 1.0868x over previous
#include <cuda_runtime.h>
#include <cuda_fp16.h>
#include <cstdint>

// ---------------------------------------------------------------------------
// Problem constants
// ---------------------------------------------------------------------------
#define SVOX 262144        // 64^3 voxels per batch
#define NB   2
#define GCH  128
#define XCH  64
#define NCTA1 4096         // NB * 2048 tiles of 128 voxels
#define EPSV 1e-5f
#define P2_CPB 296         // pass2 CTAs per batch (2*296 = 592 = 148 SMs * 4)

// SMEM strides (halfs) — R9 values
#define SA_STRIDE 136      // A tiles [k][v], 128 v + 8 pad
#define SWG_STRIDE 136     // Wg rows [n][k], 128 k + 8 pad
#define SWX_STRIDE 72      // Wx rows [n][k], 64 k + 8 pad

// pass1g smem layout (bytes)
#define G_OFF_A 0                                  // 128*136*2 = 34816
#define G_OFF_W (G_OFF_A + 128 * SA_STRIDE * 2)    // 64*136*2  = 17408
#define G_OFF_RED (G_OFF_W + 64 * SWG_STRIDE * 2)  // 8*16*4    = 512
#define G_SMEM (G_OFF_RED + 8 * 16 * 4)            // 52736 -> 3 CTAs/SM

// pass1x smem layout (bytes)
#define X_OFF_A 0                                  // 64*136*2 = 17408
#define X_OFF_W (X_OFF_A + 64 * SA_STRIDE * 2)     // 64*72*2  = 9216
#define X_OFF_RED (X_OFF_W + 64 * SWX_STRIDE * 2)
#define X_SMEM (X_OFF_RED + 8 * 16 * 4)            // 27136 -> 4 CTAs/SM

// ---------------------------------------------------------------------------
// Device scratch (allocation-free __device__ globals)
// ---------------------------------------------------------------------------
__device__ uint32_t g_sg[(size_t)NCTA1 * 4096];   // yg fp16x2, flat per-thread layout
__device__ uint32_t g_sx[(size_t)NCTA1 * 4096];   // yx fp16x2
__device__ float    g_p[NB * SVOX];               // psi-conv output p
__device__ float    g_acc[NB * 32];               // [b][ sG(8) qG(8) sX(8) qX(8) ]
__device__ float    g_accP[NB * 2];               // p sum/sumsq per batch
__device__ __align__(16) __half g_wg16[64 * SWG_STRIDE];   // prepacked fp16 Wg
__device__ __align__(16) __half g_wx16[64 * SWX_STRIDE];   // prepacked fp16 Wx

// ---------------------------------------------------------------------------
// PTX helpers
// ---------------------------------------------------------------------------
__device__ __forceinline__ uint32_t smem_to_u32(const void* smem_ptr) {
    uint32_t addr;
    asm("{ .reg .u64 tmp; cvta.to.shared.u64 tmp, %1; cvt.u32.u64 %0, tmp; }"
        : "=r"(addr) : "l"(smem_ptr));
    return addr;
}

__device__ __forceinline__ void mma16816(float* d,
                                         uint32_t a0, uint32_t a1, uint32_t a2, uint32_t a3,
                                         uint32_t b0, uint32_t b1) {
    asm volatile(
        "mma.sync.aligned.m16n8k16.row.col.f32.f16.f16.f32 "
        "{%0,%1,%2,%3}, {%4,%5,%6,%7}, {%8,%9}, {%0,%1,%2,%3};"
        : "+f"(d[0]), "+f"(d[1]), "+f"(d[2]), "+f"(d[3])
        : "r"(a0), "r"(a1), "r"(a2), "r"(a3), "r"(b0), "r"(b1));
}

__device__ __forceinline__ void ldsm_x4_trans(uint32_t& r0, uint32_t& r1,
                                              uint32_t& r2, uint32_t& r3,
                                              uint32_t addr) {
    asm volatile(
        "ldmatrix.sync.aligned.m8n8.x4.trans.shared.b16 {%0,%1,%2,%3}, [%4];"
        : "=r"(r0), "=r"(r1), "=r"(r2), "=r"(r3) : "r"(addr));
}

__device__ __forceinline__ uint32_t packf2(float a, float b) {
    __half2 h = __floats2half2_rn(a, b);
    return *reinterpret_cast<uint32_t*>(&h);
}

// ---------------------------------------------------------------------------
// setup: zero stat accumulators + prepack weights to fp16 padded images
// ---------------------------------------------------------------------------
__global__ void setup_kernel(const float* __restrict__ Wg_w,
                             const float* __restrict__ Wx_w) {
    const int tid = threadIdx.x;
    if (tid < NB * 32) g_acc[tid] = 0.0f;
    if (tid < NB * 2)  g_accP[tid] = 0.0f;
    for (int i = tid; i < 64 * SWG_STRIDE; i += 256) {
        int o = i / SWG_STRIDE, k = i % SWG_STRIDE;
        g_wg16[i] = (k < 128) ? __float2half_rn(Wg_w[o * 128 + k]) : __float2half_rn(0.0f);
    }
    for (int i = tid; i < 64 * SWX_STRIDE; i += 256) {
        int o = i / SWX_STRIDE, k = i % SWX_STRIDE;
        g_wx16[i] = (k < 64) ? __float2half_rn(Wx_w[o * 64 + k]) : __float2half_rn(0.0f);
    }
}

// ---------------------------------------------------------------------------
// pass1g (R9/R15): g conv (K=128) via mma.sync + GN stats + fp16 scratch
// ---------------------------------------------------------------------------
__global__ void __launch_bounds__(256, 3)
pass1g_kernel(const float* __restrict__ gin) {
    extern __shared__ char smem[];
    __half* sA = (__half*)(smem + G_OFF_A);
    __half* sW = (__half*)(smem + G_OFF_W);
    float*  red = (float*)(smem + G_OFF_RED);

    const int tid = threadIdx.x;
    const int w = tid >> 5, lane = tid & 31;
    const int gr = lane >> 2, tg = lane & 3;
    const int cta = blockIdx.x;
    const int b = cta >> 11;
    const int tile = cta & 2047;
    const int vb = w * 16;

    {
        const int r = tid >> 5;
        const int l = tid & 31;
        const float4* g4 = (const float4*)gin + ((size_t)b * GCH) * (SVOX / 4)
                         + (size_t)tile * 32 + l;
        #pragma unroll
        for (int it = 0; it < 16; ++it) {
            int c = it * 8 + r;
            float4 v = __ldcs(&g4[(size_t)c * (SVOX / 4)]);
            uint2 pk;
            pk.x = packf2(v.x, v.y);
            pk.y = packf2(v.z, v.w);
            *(uint2*)&sA[c * SA_STRIDE + l * 4] = pk;
        }
    }
    {
        const uint4* wg = (const uint4*)g_wg16;
        uint4* dg = (uint4*)sW;
        for (int i = tid; i < 1088; i += 256) dg[i] = wg[i];
    }
    __syncthreads();

    const uint32_t aoff2 = (uint32_t)((((lane & 7) + ((lane >> 4) & 1) * 8) * SA_STRIDE
                          + vb + ((lane >> 3) & 1) * 8) * 2);
    const uint32_t sA_u = smem_to_u32(sA) + aoff2;
    const size_t sbase4 = ((size_t)cta << 10) + (size_t)tid * 4;   // uint4 index

    #pragma unroll
    for (int half = 0; half < 2; ++half) {
        float acc[4][4];
        #pragma unroll
        for (int nt = 0; nt < 4; ++nt)
            #pragma unroll
            for (int j = 0; j < 4; ++j) acc[nt][j] = 0.0f;

        #pragma unroll
        for (int ks = 0; ks < 8; ++ks) {
            uint32_t a0, a1, a2, a3;
            ldsm_x4_trans(a0, a1, a2, a3, sA_u + (uint32_t)(ks * 16 * SA_STRIDE * 2));
            #pragma unroll
            for (int nt = 0; nt < 4; ++nt) {
                int n = (half * 4 + nt) * 8 + gr;
                uint32_t b0 = *(const uint32_t*)&sW[n * SWG_STRIDE + ks * 16 + 2 * tg];
                uint32_t b1 = *(const uint32_t*)&sW[n * SWG_STRIDE + ks * 16 + 8 + 2 * tg];
                mma16816(acc[nt], a0, a1, a2, a3, b0, b1);
            }
        }
        float stats[8];
        uint4 st[2];
        #pragma unroll
        for (int nt = 0; nt < 4; ++nt) {
            float d0 = acc[nt][0], d1 = acc[nt][1], d2 = acc[nt][2], d3 = acc[nt][3];
            stats[nt]     = d0 + d1 + d2 + d3;
            stats[4 + nt] = d0 * d0 + d1 * d1 + d2 * d2 + d3 * d3;
            ((uint32_t*)st)[nt * 2 + 0] = packf2(d0, d1);   // voxel vb+gr
            ((uint32_t*)st)[nt * 2 + 1] = packf2(d2, d3);   // voxel vb+gr+8
        }
        uint4* outg = (uint4*)g_sg + sbase4 + half * 2;
        __stcs(&outg[0], st[0]);
        __stcs(&outg[1], st[1]);

        #pragma unroll
        for (int j = 0; j < 4; ++j) {
            float t0 = stats[j], t1 = stats[4 + j];
            #pragma unroll
            for (int off = 16; off > 0; off >>= 1) {
                t0 += __shfl_xor_sync(0xFFFFFFFFu, t0, off);
                t1 += __shfl_xor_sync(0xFFFFFFFFu, t1, off);
            }
            if (lane == 0) {
                red[w * 16 + half * 4 + j]     = t0;
                red[w * 16 + 8 + half * 4 + j] = t1;
            }
        }
    }
    __syncthreads();
    if (tid < 16) {
        float t = 0.0f;
        #pragma unroll
        for (int ww = 0; ww < 8; ++ww) t += red[ww * 16 + tid];
        atomicAdd(&g_acc[b * 32 + tid], t);       // sG[8], qG[8]
    }
}

// ---------------------------------------------------------------------------
// pass1x (R9/R15): x conv (K=64), 4 CTAs/SM.
// ---------------------------------------------------------------------------
__global__ void __launch_bounds__(256, 4)
pass1x_kernel(const float* __restrict__ xin) {
    extern __shared__ char smem[];
    __half* sA = (__half*)(smem + X_OFF_A);
    __half* sW = (__half*)(smem + X_OFF_W);
    float*  red = (float*)(smem + X_OFF_RED);

    const int tid = threadIdx.x;
    const int w = tid >> 5, lane = tid & 31;
    const int gr = lane >> 2, tg = lane & 3;
    const int cta = blockIdx.x;
    const int b = cta >> 11;
    const int tile = cta & 2047;
    const int vb = w * 16;

    {
        const int r = tid >> 5;
        const int l = tid & 31;
        const float4* x4 = (const float4*)xin + ((size_t)b * XCH) * (SVOX / 4)
                         + (size_t)tile * 32 + l;
        #pragma unroll
        for (int it = 0; it < 8; ++it) {
            int c = it * 8 + r;
            float4 v = __ldcs(&x4[(size_t)c * (SVOX / 4)]);
            uint2 pk;
            pk.x = packf2(v.x, v.y);
            pk.y = packf2(v.z, v.w);
            *(uint2*)&sA[c * SA_STRIDE + l * 4] = pk;
        }
    }
    {
        const uint4* wx = (const uint4*)g_wx16;
        uint4* dx = (uint4*)sW;
        for (int i = tid; i < 576; i += 256) dx[i] = wx[i];
    }
    __syncthreads();

    const uint32_t aoff2 = (uint32_t)((((lane & 7) + ((lane >> 4) & 1) * 8) * SA_STRIDE
                          + vb + ((lane >> 3) & 1) * 8) * 2);
    const uint32_t sA_u = smem_to_u32(sA) + aoff2;
    const size_t sbase4 = ((size_t)cta << 10) + (size_t)tid * 4;

    #pragma unroll
    for (int half = 0; half < 2; ++half) {
        float acc[4][4];
        #pragma unroll
        for (int nt = 0; nt < 4; ++nt)
            #pragma unroll
            for (int j = 0; j < 4; ++j) acc[nt][j] = 0.0f;

        #pragma unroll
        for (int ks = 0; ks < 4; ++ks) {
            uint32_t a0, a1, a2, a3;
            ldsm_x4_trans(a0, a1, a2, a3, sA_u + (uint32_t)(ks * 16 * SA_STRIDE * 2));
            #pragma unroll
            for (int nt = 0; nt < 4; ++nt) {
                int n = (half * 4 + nt) * 8 + gr;
                uint32_t b0 = *(const uint32_t*)&sW[n * SWX_STRIDE + ks * 16 + 2 * tg];
                uint32_t b1 = *(const uint32_t*)&sW[n * SWX_STRIDE + ks * 16 + 8 + 2 * tg];
                mma16816(acc[nt], a0, a1, a2, a3, b0, b1);
            }
        }
        float stats[8];
        uint4 st[2];
        #pragma unroll
        for (int nt = 0; nt < 4; ++nt) {
            float d0 = acc[nt][0], d1 = acc[nt][1], d2 = acc[nt][2], d3 = acc[nt][3];
            stats[nt]     = d0 + d1 + d2 + d3;
            stats[4 + nt] = d0 * d0 + d1 * d1 + d2 * d2 + d3 * d3;
            ((uint32_t*)st)[nt * 2 + 0] = packf2(d0, d1);
            ((uint32_t*)st)[nt * 2 + 1] = packf2(d2, d3);
        }
        uint4* outx = (uint4*)g_sx + sbase4 + half * 2;
        __stcs(&outx[0], st[0]);
        __stcs(&outx[1], st[1]);

        #pragma unroll
        for (int j = 0; j < 4; ++j) {
            float t0 = stats[j], t1 = stats[4 + j];
            #pragma unroll
            for (int off = 16; off > 0; off >>= 1) {
                t0 += __shfl_xor_sync(0xFFFFFFFFu, t0, off);
                t1 += __shfl_xor_sync(0xFFFFFFFFu, t1, off);
            }
            if (lane == 0) {
                red[w * 16 + half * 4 + j]     = t0;
                red[w * 16 + 8 + half * 4 + j] = t1;
            }
        }
    }
    __syncthreads();
    if (tid < 16) {
        float t = 0.0f;
        #pragma unroll
        for (int ww = 0; ww < 8; ++ww) t += red[ww * 16 + tid];
        atomicAdd(&g_acc[b * 32 + 16 + tid], t);   // sX[8], qX[8]
    }
}

// ---------------------------------------------------------------------------
// pass2: (finA folded in) GN + leaky + psi-dot -> p, and p stats.
// Capacity-matched grid: 592 CTAs (= 148 SM x 4 at regs~64); each CTA strides
// over its batch's tiles (6-7 each). One full wave, no quantization tail.
// ---------------------------------------------------------------------------
__global__ void __launch_bounds__(256)
pass2_kernel(const float* __restrict__ psi_w,
             const float* __restrict__ gw_g, const float* __restrict__ gb_g,
             const float* __restrict__ gw_x, const float* __restrict__ gb_x) {
    __shared__ float2 spG[64], spX[64];
    __shared__ float  spw[64];
    __shared__ float  red2[8][2];

    const int tid = threadIdx.x;
    const int w = tid >> 5, lane = tid & 31;
    const int gr = lane >> 2, tg = lane & 3;
    const int blk = blockIdx.x;            // 0..2*P2_CPB-1
    const int b = blk / P2_CPB;
    const int ctaInB = blk % P2_CPB;

    if (tid < 16) {
        int conv = tid >> 3, grp = tid & 7;
        float s = g_acc[b * 32 + conv * 16 + grp];
        float q = g_acc[b * 32 + conv * 16 + 8 + grp];
        const float inv = 1.0f / (8.0f * (float)SVOX);
        float mean = s * inv;
        float var = q * inv - mean * mean;
        float rs = rsqrtf(var + EPSV);
        const float* gw = conv ? gw_x : gw_g;
        const float* gb = conv ? gb_x : gb_g;
        float2* par = conv ? spX : spG;
        #pragma unroll
        for (int c = 0; c < 8; ++c) {
            int o = grp * 8 + c;
            float sc = rs * gw[o];
            par[o] = make_float2(sc, gb[o] - mean * sc);
        }
    }
    if (tid >= 64 && tid < 128) spw[tid - 64] = psi_w[tid - 64];
    __syncthreads();

    float accS = 0.0f, accQ = 0.0f;

    for (int tile = ctaInB; tile < 2048; tile += P2_CPB) {
        const int cta = b * 2048 + tile;
        const size_t sbase4 = ((size_t)cta << 10) + (size_t)tid * 4;
        const uint4* pg4 = (const uint4*)g_sg + sbase4;
        const uint4* px4 = (const uint4*)g_sx + sbase4;
        uint32_t rg[16], rx[16];
        #pragma unroll
        for (int k2 = 0; k2 < 4; ++k2) {
            uint4 vg = __ldcs(&pg4[k2]);
            rg[4 * k2 + 0] = vg.x; rg[4 * k2 + 1] = vg.y;
            rg[4 * k2 + 2] = vg.z; rg[4 * k2 + 3] = vg.w;
            uint4 vx = __ldcs(&px4[k2]);
            rx[4 * k2 + 0] = vx.x; rx[4 * k2 + 1] = vx.y;
            rx[4 * k2 + 2] = vx.z; rx[4 * k2 + 3] = vx.w;
        }

        float pp0 = 0.0f, pp1 = 0.0f;
        #pragma unroll
        for (int nt = 0; nt < 8; ++nt) {
            int c0 = nt * 8 + 2 * tg;
            float2 G0 = spG[c0], G1 = spG[c0 + 1];
            float2 X0 = spX[c0], X1 = spX[c0 + 1];
            float w0 = spw[c0], w1 = spw[c0 + 1];
            {
                float2 yg = __half22float2(*reinterpret_cast<__half2*>(&rg[nt * 2 + 0]));
                float2 yx = __half22float2(*reinterpret_cast<__half2*>(&rx[nt * 2 + 0]));
                float a0 = fmaf(yg.x, G0.x, G0.y) + fmaf(yx.x, X0.x, X0.y);
                float a1 = fmaf(yg.y, G1.x, G1.y) + fmaf(yx.y, X1.x, X1.y);
                a0 = fmaxf(a0, 0.01f * a0);
                a1 = fmaxf(a1, 0.01f * a1);
                pp0 = fmaf(w0, a0, pp0);
                pp0 = fmaf(w1, a1, pp0);
            }
            {
                float2 yg = __half22float2(*reinterpret_cast<__half2*>(&rg[nt * 2 + 1]));
                float2 yx = __half22float2(*reinterpret_cast<__half2*>(&rx[nt * 2 + 1]));
                float a0 = fmaf(yg.x, G0.x, G0.y) + fmaf(yx.x, X0.x, X0.y);
                float a1 = fmaf(yg.y, G1.x, G1.y) + fmaf(yx.y, X1.x, X1.y);
                a0 = fmaxf(a0, 0.01f * a0);
                a1 = fmaxf(a1, 0.01f * a1);
                pp1 = fmaf(w0, a0, pp1);
                pp1 = fmaf(w1, a1, pp1);
            }
        }
        pp0 += __shfl_xor_sync(0xFFFFFFFFu, pp0, 1);
        pp0 += __shfl_xor_sync(0xFFFFFFFFu, pp0, 2);
        pp1 += __shfl_xor_sync(0xFFFFFFFFu, pp1, 1);
        pp1 += __shfl_xor_sync(0xFFFFFFFFu, pp1, 2);

        const size_t voff = (size_t)b * SVOX + (size_t)tile * 128 + w * 16;
        if (tg == 0) g_p[voff + gr]     = pp0;
        if (tg == 1) g_p[voff + gr + 8] = pp1;

        float s = (tg == 0) ? pp0 : ((tg == 1) ? pp1 : 0.0f);
        accS += s;
        accQ += s * s;
    }

    #pragma unroll
    for (int off = 16; off > 0; off >>= 1) {
        accS += __shfl_xor_sync(0xFFFFFFFFu, accS, off);
        accQ += __shfl_xor_sync(0xFFFFFFFFu, accQ, off);
    }
    if (lane == 0) { red2[w][0] = accS; red2[w][1] = accQ; }
    __syncthreads();
    if (tid == 0) {
        float ts = 0.0f, tq = 0.0f;
        #pragma unroll
        for (int ww = 0; ww < 8; ++ww) { ts += red2[ww][0]; tq += red2[ww][1]; }
        atomicAdd(&g_accP[b * 2 + 0], ts);
        atomicAdd(&g_accP[b * 2 + 1], tq);
    }
}

// ---------------------------------------------------------------------------
// pass3 (R9): (finB folded) out = x * sigmoid(z). Grid 8192, 4 ch/thread.
// ---------------------------------------------------------------------------
__global__ void __launch_bounds__(256, 8)
pass3_kernel(const float* __restrict__ xin, float* __restrict__ out,
             const float* __restrict__ pgw, const float* __restrict__ pgb) {
    const int blk = blockIdx.x;                 // 8192
    const int b = blk >> 12;
    const int cchunk = (blk >> 8) & 15;
    const int q = ((blk & 255) << 8) + threadIdx.x;   // quad 0..65535

    float sB = g_accP[b * 2], qB = g_accP[b * 2 + 1];
    const float inv = 1.0f / (float)SVOX;
    float mean = sB * inv;
    float var = qB * inv - mean * mean;
    float rs = rsqrtf(var + EPSV);
    float zsc = rs * pgw[0];
    float zsh = pgb[0] - mean * zsc;

    const float4* xp = (const float4*)xin
                     + ((size_t)b * 64 + (size_t)cchunk * 4) * 65536 + q;
    float4* op = (float4*)out
               + ((size_t)b * 64 + (size_t)cchunk * 4) * 65536 + q;

    float4 pv = *((const float4*)g_p + (size_t)b * 65536 + q);
    float4 xv[4];
    #pragma unroll
    for (int c = 0; c < 4; c++) xv[c] = __ldcs(&xp[(size_t)c * 65536]);

    float4 ps;
    {
        float z0 = fmaf(pv.x, zsc, zsh);
        float z1 = fmaf(pv.y, zsc, zsh);
        float z2 = fmaf(pv.z, zsc, zsh);
        float z3 = fmaf(pv.w, zsc, zsh);
        ps.x = __fdividef(1.0f, 1.0f + __expf(-z0));
        ps.y = __fdividef(1.0f, 1.0f + __expf(-z1));
        ps.z = __fdividef(1.0f, 1.0f + __expf(-z2));
        ps.w = __fdividef(1.0f, 1.0f + __expf(-z3));
    }

    #pragma unroll
    for (int c = 0; c < 4; c++) {
        float4 ov;
        ov.x = xv[c].x * ps.x; ov.y = xv[c].y * ps.y;
        ov.z = xv[c].z * ps.z; ov.w = xv[c].w * ps.w;
        __stcs(&op[(size_t)c * 65536], ov);
    }
}

// ---------------------------------------------------------------------------
// launch
// ---------------------------------------------------------------------------
extern "C" void kernel_launch(void* const* d_in, const int* in_sizes, int n_in,
                              void* d_out, int out_size) {
    (void)in_sizes; (void)n_in; (void)out_size;
    const float* g        = (const float*)d_in[0];
    const float* x        = (const float*)d_in[1];
    const float* Wg_w     = (const float*)d_in[2];
    const float* Wg_gn_w  = (const float*)d_in[3];
    const float* Wg_gn_b  = (const float*)d_in[4];
    const float* Wx_w     = (const float*)d_in[5];
    const float* Wx_gn_w  = (const float*)d_in[6];
    const float* Wx_gn_b  = (const float*)d_in[7];
    const float* psi_w    = (const float*)d_in[8];
    const float* psi_gn_w = (const float*)d_in[9];
    const float* psi_gn_b = (const float*)d_in[10];
    float* out = (float*)d_out;

    cudaFuncSetAttribute(pass1g_kernel, cudaFuncAttributeMaxDynamicSharedMemorySize,
                         G_SMEM);
    cudaFuncSetAttribute(pass1x_kernel, cudaFuncAttributeMaxDynamicSharedMemorySize,
                         X_SMEM);

    setup_kernel<<<1, 256>>>(Wg_w, Wx_w);
    pass1g_kernel<<<NCTA1, 256, G_SMEM>>>(g);
    pass1x_kernel<<<NCTA1, 256, X_SMEM>>>(x);
    pass2_kernel<<<NB * P2_CPB, 256>>>(psi_w, Wg_gn_w, Wg_gn_b, Wx_gn_w, Wx_gn_b);
    pass3_kernel<<<8192, 256>>>(x, out, psi_gn_w, psi_gn_b);
}